// round 1
// baseline (speedup 1.0000x reference)
#include <cuda_runtime.h>
#include <cuda_bf16.h>
#include <math.h>

// Problem dims
#define LYR 3
#define HH  8
#define DD  128
#define DKK 16
#define FF  512
#define BB  32
#define NN  512
#define FIN 16
#define OUTD 3
#define ROWS (BB*NN)          // 16384
#define QKVN (3*DD)           // 384
#define ATTN_SCALE 0.25f      // 1/sqrt(16)

// ---------------- scratch (__device__ globals; no allocation) ----------------
__device__ float g_h[ROWS*DD];       // hidden state [16384,128]
__device__ float g_qkv[ROWS*QKVN];   // fused QKV    [16384,384]
__device__ float g_heads[ROWS*DD];   // attn output  [16384,128]
__device__ float g_ff[ROWS*FF];      // ffn hidden   [16384,512]
__device__ float g_wt[LYR*DD*QKVN];  // repacked QKV weights [3][128][384]
__device__ float g_hpp[BB*DD];       // pooled proj  [32,128]

// ---------------- weight repack: Wq/Wk/Wv [L,H,D,DK] -> [L][D][384] ----------
__global__ void repack_kernel(const float* __restrict__ Wq,
                              const float* __restrict__ Wk,
                              const float* __restrict__ Wv,
                              float* __restrict__ wt)
{
    int idx = blockIdx.x * 256 + threadIdx.x;
    if (idx >= LYR*DD*QKVN) return;
    int l = idx / (DD*QKVN);
    int r = idx % (DD*QKVN);
    int d = r / QKVN, c = r % QKVN;
    int sel = c >> 7;          // 0=Q 1=K 2=V
    int hc  = c & 127;
    int hh  = hc >> 4, kk = hc & 15;
    const float* W = (sel == 0) ? Wq : (sel == 1) ? Wk : Wv;
    wt[idx] = W[(((l*HH + hh)*DD) + d)*DKK + kk];
}

// ---------------- generic fp32 GEMM: C = opt_relu(res + A@B + bias) ----------
// A [M,K] rowmajor, B [K,N] rowmajor. Tile 128x64x16, 256 threads, 8x4/thread.
// Requires M%128==0, N%64==0, K%16==0 (all shapes here satisfy this).
#define GBM 128
#define GBN 64
#define GBK 16

__global__ __launch_bounds__(256)
void gemm_kernel(const float* __restrict__ A, const float* __restrict__ B,
                 const float* __restrict__ bias, const float* __restrict__ res,
                 float* __restrict__ C, int M, int K, int N, int do_relu)
{
    __shared__ float As[GBK][GBM + 4];   // transposed A tile (row stride 132 keeps 16B align)
    __shared__ float Bs[GBK][GBN];

    const int tid  = threadIdx.x;
    const int brow = blockIdx.y * GBM;
    const int bcol = blockIdx.x * GBN;
    const int ty   = tid >> 4;           // 0..15 -> 8-row strip
    const int tx   = tid & 15;           // 0..15 -> 4-col strip

    float acc[8][4];
#pragma unroll
    for (int i = 0; i < 8; i++)
#pragma unroll
        for (int j = 0; j < 4; j++) acc[i][j] = 0.f;

    for (int k0 = 0; k0 < K; k0 += GBK) {
        // load A tile: 128x16 = 2048 floats, 2 float4/thread, store transposed
#pragma unroll
        for (int r = 0; r < 2; r++) {
            int fid = tid + r * 256;
            int ar = fid >> 2, ac = (fid & 3) << 2;
            float4 a4 = *(const float4*)(A + (size_t)(brow + ar) * K + k0 + ac);
            As[ac + 0][ar] = a4.x; As[ac + 1][ar] = a4.y;
            As[ac + 2][ar] = a4.z; As[ac + 3][ar] = a4.w;
        }
        // load B tile: 16x64 = 1024 floats, 1 float4/thread
        {
            int brr = tid >> 4, bcc = (tid & 15) << 2;
            *(float4*)&Bs[brr][bcc] =
                *(const float4*)(B + (size_t)(k0 + brr) * N + bcol + bcc);
        }
        __syncthreads();

#pragma unroll
        for (int kk = 0; kk < GBK; kk++) {
            float a[8], b[4];
            *(float4*)&a[0] = *(float4*)&As[kk][ty * 8];
            *(float4*)&a[4] = *(float4*)&As[kk][ty * 8 + 4];
            *(float4*)&b[0] = *(float4*)&Bs[kk][tx * 4];
#pragma unroll
            for (int i = 0; i < 8; i++)
#pragma unroll
                for (int j = 0; j < 4; j++)
                    acc[i][j] += a[i] * b[j];
        }
        __syncthreads();
    }

    // epilogue
    float4 bb = make_float4(0.f, 0.f, 0.f, 0.f);
    if (bias) bb = *(const float4*)(bias + bcol + tx * 4);
#pragma unroll
    for (int i = 0; i < 8; i++) {
        int row = brow + ty * 8 + i;
        size_t off = (size_t)row * N + bcol + tx * 4;
        float4 v = make_float4(acc[i][0] + bb.x, acc[i][1] + bb.y,
                               acc[i][2] + bb.z, acc[i][3] + bb.w);
        if (res) {
            float4 rv = *(const float4*)(res + off);
            v.x += rv.x; v.y += rv.y; v.z += rv.z; v.w += rv.w;
        }
        if (do_relu) {
            v.x = fmaxf(v.x, 0.f); v.y = fmaxf(v.y, 0.f);
            v.z = fmaxf(v.z, 0.f); v.w = fmaxf(v.w, 0.f);
        }
        *(float4*)(C + off) = v;
    }
}

// ---------------- flash attention: 1 CTA per (b,h), 1 thread per query row ---
// qkv layout per row: [0:128)=Q(h*16+k), [128:256)=K, [256:384)=V
__global__ __launch_bounds__(512)
void attn_kernel(const float* __restrict__ qkv, const int* __restrict__ mask,
                 float* __restrict__ heads)
{
    extern __shared__ float sm[];
    float* Ks = sm;                 // [512][16]
    float* Vs = sm + NN * DKK;      // [512][16]

    const int b  = blockIdx.x >> 3;
    const int hh = blockIdx.x & 7;
    const int tid = threadIdx.x;

    // cooperative K/V load: 2048 float4 per matrix, 4 per thread
    for (int i = tid; i < NN * 4; i += 512) {
        int n = i >> 2, k4 = (i & 3) << 2;
        const float* src = qkv + (size_t)(b * NN + n) * QKVN + DD + hh * DKK + k4;
        *(float4*)&Ks[n * DKK + k4] = *(const float4*)src;
        *(float4*)&Vs[n * DKK + k4] = *(const float4*)(src + DD);
    }
    __syncthreads();

    const int q = tid;
    float qv[DKK];
    {
        const float* qp = qkv + (size_t)(b * NN + q) * QKVN + hh * DKK;
#pragma unroll
        for (int i = 0; i < DKK; i += 4) *(float4*)&qv[i] = *(const float4*)(qp + i);
    }
    const int* mrow = mask + (size_t)(b * NN + q) * NN;

    float m = -1e30f, l = 0.f;
    float acc[DKK];
#pragma unroll
    for (int k = 0; k < DKK; k++) acc[k] = 0.f;

    for (int n0 = 0; n0 < NN; n0 += 4) {
        int4 mm = *(const int4*)(mrow + n0);
        int mk[4] = {mm.x, mm.y, mm.z, mm.w};
#pragma unroll
        for (int j = 0; j < 4; j++) {
            if (mk[j]) {
                int n = n0 + j;
                const float* kr = &Ks[n * DKK];
                float s = 0.f;
#pragma unroll
                for (int k = 0; k < DKK; k++) s += qv[k] * kr[k];
                s *= ATTN_SCALE;
                if (s > m) {            // rare after warm-up: rescale state
                    float c = __expf(m - s);
                    l *= c;
#pragma unroll
                    for (int k = 0; k < DKK; k++) acc[k] *= c;
                    m = s;
                }
                float p = __expf(s - m);
                l += p;
                const float* vr = &Vs[n * DKK];
#pragma unroll
                for (int k = 0; k < DKK; k++) acc[k] += p * vr[k];
            }
        }
    }

    float inv = 1.f / l;   // every row has >=1 valid entry (diagonal)
    float* out = heads + (size_t)(b * NN + q) * DD + hh * DKK;
#pragma unroll
    for (int k = 0; k < DKK; k += 4) {
        float4 v = make_float4(acc[k] * inv, acc[k + 1] * inv,
                               acc[k + 2] * inv, acc[k + 3] * inv);
        *(float4*)(out + k) = v;
    }
}

// ---------------- pooling + Wp: hpp[b] = (mean_n h[b,n]) @ Wp ----------------
__global__ void pool_kernel(const float* __restrict__ h, const float* __restrict__ Wp,
                            float* __restrict__ hpp)
{
    __shared__ float mean[DD];
    int b = blockIdx.x, d = threadIdx.x;
    const float* hp = h + (size_t)b * NN * DD + d;
    float s = 0.f;
    for (int n = 0; n < NN; n++) s += hp[(size_t)n * DD];
    mean[d] = s * (1.f / (float)NN);
    __syncthreads();
    float acc = 0.f;
#pragma unroll 4
    for (int i = 0; i < DD; i++) acc += mean[i] * Wp[i * DD + d];
    hpp[b * DD + d] = acc;
}

// ---------------- readout: out = relu(concat(hpp[b], h[b,n])) @ Wr + br ------
__global__ void readout_kernel(const float* __restrict__ h, const float* __restrict__ hpp,
                               const float* __restrict__ Wr, const float* __restrict__ br,
                               float* __restrict__ out)
{
    __shared__ float WrS[2 * DD * OUTD];
    __shared__ float brS[OUTD];
    int tid = threadIdx.x;                  // 128
    for (int i = tid; i < 2 * DD * OUTD; i += 128) WrS[i] = Wr[i];
    if (tid < OUTD) brS[tid] = br[tid];
    __syncthreads();

    int row = blockIdx.x * 128 + tid;       // blocks of 128 rows, all same b
    int b = row >> 9;
    float a0 = brS[0], a1 = brS[1], a2 = brS[2];
    const float* hp = hpp + b * DD;
#pragma unroll 4
    for (int i = 0; i < DD; i++) {
        float f = fmaxf(hp[i], 0.f);
        a0 += f * WrS[i * 3 + 0]; a1 += f * WrS[i * 3 + 1]; a2 += f * WrS[i * 3 + 2];
    }
    const float* hr = h + (size_t)row * DD;
#pragma unroll 4
    for (int i = 0; i < DD; i++) {
        float f = fmaxf(hr[i], 0.f);
        a0 += f * WrS[(DD + i) * 3 + 0];
        a1 += f * WrS[(DD + i) * 3 + 1];
        a2 += f * WrS[(DD + i) * 3 + 2];
    }
    out[row * 3 + 0] = a0; out[row * 3 + 1] = a1; out[row * 3 + 2] = a2;
}

// ---------------- host launcher ----------------------------------------------
extern "C" void kernel_launch(void* const* d_in, const int* in_sizes, int n_in,
                              void* d_out, int out_size)
{
    const float* x    = (const float*)d_in[0];
    const int*   mask = (const int*)  d_in[1];
    const float* We   = (const float*)d_in[2];
    const float* Wq   = (const float*)d_in[3];
    const float* Wk   = (const float*)d_in[4];
    const float* Wv   = (const float*)d_in[5];
    const float* Wout = (const float*)d_in[6];
    const float* Wff1 = (const float*)d_in[7];
    const float* bff1 = (const float*)d_in[8];
    const float* Wff2 = (const float*)d_in[9];
    const float* bff2 = (const float*)d_in[10];
    const float* Wp   = (const float*)d_in[11];
    const float* Wr   = (const float*)d_in[12];
    const float* br   = (const float*)d_in[13];
    float* out = (float*)d_out;

    float *h, *qkv, *heads, *ff, *wt, *hpp;
    cudaGetSymbolAddress((void**)&h,     g_h);
    cudaGetSymbolAddress((void**)&qkv,   g_qkv);
    cudaGetSymbolAddress((void**)&heads, g_heads);
    cudaGetSymbolAddress((void**)&ff,    g_ff);
    cudaGetSymbolAddress((void**)&wt,    g_wt);
    cudaGetSymbolAddress((void**)&hpp,   g_hpp);

    cudaFuncSetAttribute(attn_kernel,
                         cudaFuncAttributeMaxDynamicSharedMemorySize,
                         2 * NN * DKK * sizeof(float));

    // repack QKV weights for all layers
    repack_kernel<<<(LYR*DD*QKVN + 255) / 256, 256>>>(Wq, Wk, Wv, wt);

    // embed: h = relu(x @ We)   [16384,16]@[16,128]
    gemm_kernel<<<dim3(DD / GBN, ROWS / GBM), 256>>>(
        x, We, nullptr, nullptr, h, ROWS, FIN, DD, 1);

    for (int l = 0; l < LYR; l++) {
        // fused QKV: [16384,128]@[128,384]
        gemm_kernel<<<dim3(QKVN / GBN, ROWS / GBM), 256>>>(
            h, wt + (size_t)l * DD * QKVN, nullptr, nullptr, qkv,
            ROWS, DD, QKVN, 0);

        // attention
        attn_kernel<<<BB * HH, 512, 2 * NN * DKK * sizeof(float)>>>(qkv, mask, heads);

        // h = h + heads @ Wout[l]   (Wout[l] is [H*DK,128] rowmajor already)
        gemm_kernel<<<dim3(DD / GBN, ROWS / GBM), 256>>>(
            heads, Wout + (size_t)l * HH * DKK * DD, nullptr, h, h,
            ROWS, DD, DD, 0);

        // ff = relu(h @ Wff1[l] + bff1[l])
        gemm_kernel<<<dim3(FF / GBN, ROWS / GBM), 256>>>(
            h, Wff1 + (size_t)l * DD * FF, bff1 + (size_t)l * FF, nullptr, ff,
            ROWS, DD, FF, 1);

        // h = h + ff @ Wff2[l] + bff2[l]
        gemm_kernel<<<dim3(DD / GBN, ROWS / GBM), 256>>>(
            ff, Wff2 + (size_t)l * FF * DD, bff2 + (size_t)l * DD, h, h,
            ROWS, FF, DD, 0);
    }

    // pooled projection + readout
    pool_kernel<<<BB, DD>>>(h, Wp, hpp);
    readout_kernel<<<ROWS / 128, 128>>>(h, hpp, Wr, br, out);
}

// round 2
// speedup vs baseline: 2.1212x; 2.1212x over previous
#include <cuda_runtime.h>
#include <cuda_bf16.h>
#include <math.h>
#include <stdint.h>

// Problem dims
#define LYR 3
#define HH  8
#define DD  128
#define DKK 16
#define FF  512
#define BB  32
#define NN  512
#define FIN 16
#define OUTD 3
#define ROWS (BB*NN)          // 16384
#define QKVN (3*DD)           // 384
#define SCL (0.25f * 1.44269504089f)   // attn scale * log2(e)
#define MASKVAL (-2e30f)
#define MINIT   (-1e30f)

// ---------------- scratch (__device__ globals; no allocation) ----------------
__device__ float    g_h[ROWS*DD];
__device__ float    g_qkv[ROWS*QKVN];
__device__ float    g_heads[ROWS*DD];
__device__ float    g_ff[ROWS*FF];
__device__ float    g_wt[LYR*DD*QKVN];
__device__ float    g_hpp[BB*DD];
__device__ unsigned g_mpack[BB*NN*(NN/32)];   // bit-packed mask [32][512][16]

// ---------------- helpers ----------------------------------------------------
__device__ __forceinline__ uint32_t f2u(float x){ return __float_as_uint(x); }

__device__ __forceinline__ float cvt_tf32(float x){
    uint32_t u; asm("cvt.rna.tf32.f32 %0, %1;" : "=r"(u) : "f"(x));
    return __uint_as_float(u);
}
__device__ __forceinline__ float4 cvt_tf32_4(float4 v){
    return make_float4(cvt_tf32(v.x), cvt_tf32(v.y), cvt_tf32(v.z), cvt_tf32(v.w));
}
__device__ __forceinline__ uint32_t bf16x2(float hi, float lo){
    uint32_t r; asm("cvt.rn.bf16x2.f32 %0, %1, %2;" : "=r"(r) : "f"(hi), "f"(lo));
    return r;
}
__device__ __forceinline__ void mma_tf32(float c[4], const uint32_t a[4], const uint32_t b[2]){
    asm volatile("mma.sync.aligned.m16n8k8.row.col.f32.tf32.tf32.f32 "
        "{%0,%1,%2,%3},{%4,%5,%6,%7},{%8,%9},{%0,%1,%2,%3};\n"
        : "+f"(c[0]),"+f"(c[1]),"+f"(c[2]),"+f"(c[3])
        : "r"(a[0]),"r"(a[1]),"r"(a[2]),"r"(a[3]),"r"(b[0]),"r"(b[1]));
}
__device__ __forceinline__ void mma_bf16(float c[4], const uint32_t a[4], uint32_t b0, uint32_t b1){
    asm volatile("mma.sync.aligned.m16n8k16.row.col.f32.bf16.bf16.f32 "
        "{%0,%1,%2,%3},{%4,%5,%6,%7},{%8,%9},{%0,%1,%2,%3};\n"
        : "+f"(c[0]),"+f"(c[1]),"+f"(c[2]),"+f"(c[3])
        : "r"(a[0]),"r"(a[1]),"r"(a[2]),"r"(a[3]),"r"(b0),"r"(b1));
}

// ---------------- weight repack: Wq/Wk/Wv [L,H,D,DK] -> [L][D][384] ----------
__global__ void repack_kernel(const float* __restrict__ Wq,
                              const float* __restrict__ Wk,
                              const float* __restrict__ Wv,
                              float* __restrict__ wt)
{
    int idx = blockIdx.x * 256 + threadIdx.x;
    if (idx >= LYR*DD*QKVN) return;
    int l = idx / (DD*QKVN);
    int r = idx % (DD*QKVN);
    int d = r / QKVN, c = r % QKVN;
    int sel = c >> 7;
    int hc  = c & 127;
    int hh  = hc >> 4, kk = hc & 15;
    const float* W = (sel == 0) ? Wq : (sel == 1) ? Wk : Wv;
    wt[idx] = W[(((l*HH + hh)*DD) + d)*DKK + kk];
}

// ---------------- mask bit-pack: [32][512][512] int -> [32][512][16] u32 -----
__global__ void maskpack_kernel(const int* __restrict__ mask, unsigned* __restrict__ mpack)
{
    int idx = blockIdx.x * 256 + threadIdx.x;
    if (idx >= BB*NN*(NN/32)) return;
    const int* src = mask + (size_t)idx * 32;
    unsigned v = 0;
#pragma unroll
    for (int j = 0; j < 32; j += 4){
        int4 mm = *(const int4*)(src + j);
        v |= ((unsigned)(mm.x != 0)) << (j    );
        v |= ((unsigned)(mm.y != 0)) << (j + 1);
        v |= ((unsigned)(mm.z != 0)) << (j + 2);
        v |= ((unsigned)(mm.w != 0)) << (j + 3);
    }
    mpack[idx] = v;
}

// ---------------- tf32 tensor-core GEMM: C = opt_relu(res + A@B + bias) ------
// A [M,K] rowmajor fp32, B [K,N] rowmajor fp32. BM=128 BN=64 BK=16.
// 256 threads = 8 warps (4m x 2n), warp tile 32x32, mma m16n8k8 tf32.
__global__ __launch_bounds__(256)
void gemm_tf32(const float* __restrict__ A, const float* __restrict__ B,
               const float* __restrict__ bias, const float* __restrict__ res,
               float* __restrict__ C, int M, int K, int N, int do_relu)
{
    __shared__ float As[128][20];
    __shared__ float Bs[64][20];

    const int tid  = threadIdx.x;
    const int lane = tid & 31;
    const int wid  = tid >> 5;
    const int wm   = wid >> 1;     // 0..3
    const int wn   = wid & 1;      // 0..1
    const int brow = blockIdx.y * 128;
    const int bcol = blockIdx.x * 64;

    // fill assignments
    const int ar  = tid >> 1;            // 0..127
    const int akc = (tid & 1) * 8;       // 0 or 8
    const int bk  = tid & 15;            // 0..15
    const int bnb = (tid >> 4) * 4;      // 0..60

    const float* Aptr = A + (size_t)(brow + ar) * K + akc;
    const float* Bptr = B + (size_t)bk * N + bcol + bnb;

    float4 pa0 = *(const float4*)(Aptr);
    float4 pa1 = *(const float4*)(Aptr + 4);
    float4 pb  = *(const float4*)(Bptr);

    float c[2][4][4];
#pragma unroll
    for (int mt = 0; mt < 2; mt++)
#pragma unroll
        for (int nt = 0; nt < 4; nt++)
#pragma unroll
            for (int i = 0; i < 4; i++) c[mt][nt][i] = 0.f;

    const int ntile = K / 16;
    for (int t = 0; t < ntile; t++){
        float4 qa0 = cvt_tf32_4(pa0), qa1 = cvt_tf32_4(pa1), qb = cvt_tf32_4(pb);
        *(float4*)&As[ar][akc]     = qa0;
        *(float4*)&As[ar][akc + 4] = qa1;
        Bs[bnb + 0][bk] = qb.x; Bs[bnb + 1][bk] = qb.y;
        Bs[bnb + 2][bk] = qb.z; Bs[bnb + 3][bk] = qb.w;
        __syncthreads();

        if (t + 1 < ntile){
            pa0 = *(const float4*)(Aptr + (t + 1) * 16);
            pa1 = *(const float4*)(Aptr + (t + 1) * 16 + 4);
            pb  = *(const float4*)(Bptr + (size_t)(t + 1) * 16 * N);
        }

#pragma unroll
        for (int ks = 0; ks < 2; ks++){
            const int kb = ks * 8;
            uint32_t a[2][4], b[4][2];
#pragma unroll
            for (int mt = 0; mt < 2; mt++){
                int r  = wm * 32 + mt * 16 + (lane >> 2);
                int cc = kb + (lane & 3);
                a[mt][0] = f2u(As[r][cc]);
                a[mt][1] = f2u(As[r + 8][cc]);
                a[mt][2] = f2u(As[r][cc + 4]);
                a[mt][3] = f2u(As[r + 8][cc + 4]);
            }
#pragma unroll
            for (int nt = 0; nt < 4; nt++){
                int n  = wn * 32 + nt * 8 + (lane >> 2);
                int kk = kb + (lane & 3);
                b[nt][0] = f2u(Bs[n][kk]);
                b[nt][1] = f2u(Bs[n][kk + 4]);
            }
#pragma unroll
            for (int mt = 0; mt < 2; mt++)
#pragma unroll
                for (int nt = 0; nt < 4; nt++)
                    mma_tf32(c[mt][nt], a[mt], b[nt]);
        }
        __syncthreads();
    }

    // epilogue
#pragma unroll
    for (int mt = 0; mt < 2; mt++){
        int r0 = brow + wm * 32 + mt * 16 + (lane >> 2);
#pragma unroll
        for (int nt = 0; nt < 4; nt++){
            int col = bcol + wn * 32 + nt * 8 + (lane & 3) * 2;
            float2 bb = make_float2(0.f, 0.f);
            if (bias) bb = *(const float2*)(bias + col);
            size_t off0 = (size_t)r0 * N + col;
            size_t off1 = (size_t)(r0 + 8) * N + col;
            float2 v0 = make_float2(c[mt][nt][0] + bb.x, c[mt][nt][1] + bb.y);
            float2 v1 = make_float2(c[mt][nt][2] + bb.x, c[mt][nt][3] + bb.y);
            if (res){
                float2 r0v = *(const float2*)(res + off0);
                float2 r1v = *(const float2*)(res + off1);
                v0.x += r0v.x; v0.y += r0v.y; v1.x += r1v.x; v1.y += r1v.y;
            }
            if (do_relu){
                v0.x = fmaxf(v0.x, 0.f); v0.y = fmaxf(v0.y, 0.f);
                v1.x = fmaxf(v1.x, 0.f); v1.y = fmaxf(v1.y, 0.f);
            }
            *(float2*)(C + off0) = v0;
            *(float2*)(C + off1) = v1;
        }
    }
}

// ---------------- flash attention via MMA ------------------------------------
// CTA per (b,h), 8 warps. K as tf32 in smem [512][20]; V bf16 transposed [16][520].
// S = Q K^T (tf32 mma), masked online softmax (log2 domain), P·V (bf16 mma).
#define ATTN_SMEM (NN*20*4 + DKK*520*2)

__global__ __launch_bounds__(256)
void attn_mma(const float* __restrict__ qkv, const unsigned* __restrict__ mpack,
              float* __restrict__ heads)
{
    extern __shared__ char smraw[];
    float* Ks = (float*)smraw;                              // [512][20]
    __nv_bfloat16* Vs = (__nv_bfloat16*)(smraw + NN*20*4);  // [16][520]

    const int b = blockIdx.x >> 3, h = blockIdx.x & 7;
    const int tid = threadIdx.x, lane = tid & 31, wid = tid >> 5;

    // fill K (tf32) and V (bf16, transposed)
    for (int i = tid; i < NN * 4; i += 256){
        int row = i >> 2, c4 = (i & 3) << 2;
        const float* base = qkv + (size_t)(b * NN + row) * QKVN + h * DKK;
        float4 kk = *(const float4*)(base + DD + c4);
        Ks[row * 20 + c4 + 0] = cvt_tf32(kk.x);
        Ks[row * 20 + c4 + 1] = cvt_tf32(kk.y);
        Ks[row * 20 + c4 + 2] = cvt_tf32(kk.z);
        Ks[row * 20 + c4 + 3] = cvt_tf32(kk.w);
        float4 vv = *(const float4*)(base + 2 * DD + c4);
        Vs[(c4 + 0) * 520 + row] = __float2bfloat16(vv.x);
        Vs[(c4 + 1) * 520 + row] = __float2bfloat16(vv.y);
        Vs[(c4 + 2) * 520 + row] = __float2bfloat16(vv.z);
        Vs[(c4 + 3) * 520 + row] = __float2bfloat16(vv.w);
    }
    __syncthreads();

    const float* Qb = qkv + (size_t)(b * NN) * QKVN + h * DKK;

    for (int qb = 0; qb < 4; qb++){
        const int qrow = qb * 128 + wid * 16 + (lane >> 2);   // low row of frag

        // Q fragments (2 k-steps), direct from gmem, tf32
        uint32_t aq[2][4];
#pragma unroll
        for (int ks = 0; ks < 2; ks++){
            int cc = ks * 8 + (lane & 3);
            aq[ks][0] = f2u(cvt_tf32(Qb[(size_t)qrow * QKVN + cc]));
            aq[ks][1] = f2u(cvt_tf32(Qb[(size_t)(qrow + 8) * QKVN + cc]));
            aq[ks][2] = f2u(cvt_tf32(Qb[(size_t)qrow * QKVN + cc + 4]));
            aq[ks][3] = f2u(cvt_tf32(Qb[(size_t)(qrow + 8) * QKVN + cc + 4]));
        }

        float m0 = MINIT, m1 = MINIT, l0 = 0.f, l1 = 0.f;
        float o[2][4];
#pragma unroll
        for (int vt = 0; vt < 2; vt++)
#pragma unroll
            for (int i = 0; i < 4; i++) o[vt][i] = 0.f;

        for (int kb = 0; kb < 8; kb++){
            // ---- S tile 16x64 (8 n-tiles) ----
            float s[8][4];
#pragma unroll
            for (int nt = 0; nt < 8; nt++){
                s[nt][0] = s[nt][1] = s[nt][2] = s[nt][3] = 0.f;
#pragma unroll
                for (int ks = 0; ks < 2; ks++){
                    uint32_t bb[2];
                    int n  = kb * 64 + nt * 8 + (lane >> 2);
                    int kk = ks * 8 + (lane & 3);
                    bb[0] = f2u(Ks[n * 20 + kk]);
                    bb[1] = f2u(Ks[n * 20 + kk + 4]);
                    mma_tf32(s[nt], aq[ks], bb);
                }
            }
            // ---- mask + scale (log2 domain) ----
            const unsigned* mpr = mpack + ((size_t)(b * NN + qrow) << 4) + kb * 2;
            unsigned mw00 = mpr[0], mw01 = mpr[1];
            unsigned mw10 = mpr[8 * 16], mw11 = mpr[8 * 16 + 1];
#pragma unroll
            for (int nt = 0; nt < 8; nt++){
                int cb  = nt * 8 + (lane & 3) * 2;   // 0..62, even
                unsigned wlo = (cb & 32) ? mw01 : mw00;
                unsigned whi = (cb & 32) ? mw11 : mw10;
                int bit = cb & 31;
                s[nt][0] = ((wlo >> bit)       & 1) ? s[nt][0] * SCL : MASKVAL;
                s[nt][1] = ((wlo >> (bit + 1)) & 1) ? s[nt][1] * SCL : MASKVAL;
                s[nt][2] = ((whi >> bit)       & 1) ? s[nt][2] * SCL : MASKVAL;
                s[nt][3] = ((whi >> (bit + 1)) & 1) ? s[nt][3] * SCL : MASKVAL;
            }
            // ---- online softmax ----
            float rx0 = MASKVAL, rx1 = MASKVAL;
#pragma unroll
            for (int nt = 0; nt < 8; nt++){
                rx0 = fmaxf(rx0, fmaxf(s[nt][0], s[nt][1]));
                rx1 = fmaxf(rx1, fmaxf(s[nt][2], s[nt][3]));
            }
            rx0 = fmaxf(rx0, __shfl_xor_sync(0xffffffffu, rx0, 1));
            rx0 = fmaxf(rx0, __shfl_xor_sync(0xffffffffu, rx0, 2));
            rx1 = fmaxf(rx1, __shfl_xor_sync(0xffffffffu, rx1, 1));
            rx1 = fmaxf(rx1, __shfl_xor_sync(0xffffffffu, rx1, 2));
            float nm0 = fmaxf(m0, rx0), nm1 = fmaxf(m1, rx1);
            float f0 = exp2f(m0 - nm0), f1 = exp2f(m1 - nm1);
            m0 = nm0; m1 = nm1;
            l0 *= f0;  l1 *= f1;
#pragma unroll
            for (int vt = 0; vt < 2; vt++){
                o[vt][0] *= f0; o[vt][1] *= f0;
                o[vt][2] *= f1; o[vt][3] *= f1;
            }
#pragma unroll
            for (int nt = 0; nt < 8; nt++){
                s[nt][0] = exp2f(s[nt][0] - m0);
                s[nt][1] = exp2f(s[nt][1] - m0);
                s[nt][2] = exp2f(s[nt][2] - m1);
                s[nt][3] = exp2f(s[nt][3] - m1);
                l0 += s[nt][0] + s[nt][1];
                l1 += s[nt][2] + s[nt][3];
            }
            // ---- P @ V (bf16 mma, C-frag -> A-frag register repack) ----
#pragma unroll
            for (int kt = 0; kt < 4; kt++){
                uint32_t pa[4];
                pa[0] = bf16x2(s[2 * kt][1],     s[2 * kt][0]);
                pa[1] = bf16x2(s[2 * kt][3],     s[2 * kt][2]);
                pa[2] = bf16x2(s[2 * kt + 1][1], s[2 * kt + 1][0]);
                pa[3] = bf16x2(s[2 * kt + 1][3], s[2 * kt + 1][2]);
#pragma unroll
                for (int vt = 0; vt < 2; vt++){
                    int dk = vt * 8 + (lane >> 2);
                    int kv = kb * 64 + kt * 16 + (lane & 3) * 2;
                    uint32_t b0 = *(const uint32_t*)&Vs[dk * 520 + kv];
                    uint32_t b1 = *(const uint32_t*)&Vs[dk * 520 + kv + 8];
                    mma_bf16(o[vt], pa, b0, b1);
                }
            }
        } // kb

        // finalize rows
        l0 += __shfl_xor_sync(0xffffffffu, l0, 1);
        l0 += __shfl_xor_sync(0xffffffffu, l0, 2);
        l1 += __shfl_xor_sync(0xffffffffu, l1, 1);
        l1 += __shfl_xor_sync(0xffffffffu, l1, 2);
        float i0 = 1.f / l0, i1 = 1.f / l1;
#pragma unroll
        for (int vt = 0; vt < 2; vt++){
            int col = h * DKK + vt * 8 + (lane & 3) * 2;
            float2 v0 = make_float2(o[vt][0] * i0, o[vt][1] * i0);
            float2 v1 = make_float2(o[vt][2] * i1, o[vt][3] * i1);
            *(float2*)&heads[(size_t)(b * NN + qrow) * DD + col]     = v0;
            *(float2*)&heads[(size_t)(b * NN + qrow + 8) * DD + col] = v1;
        }
    } // qb
}

// ---------------- pooling + Wp ----------------------------------------------
__global__ void pool_kernel(const float* __restrict__ h, const float* __restrict__ Wp,
                            float* __restrict__ hpp)
{
    __shared__ float mean[DD];
    int b = blockIdx.x, d = threadIdx.x;
    const float* hp = h + (size_t)b * NN * DD + d;
    float s = 0.f;
    for (int n = 0; n < NN; n++) s += hp[(size_t)n * DD];
    mean[d] = s * (1.f / (float)NN);
    __syncthreads();
    float acc = 0.f;
#pragma unroll 4
    for (int i = 0; i < DD; i++) acc += mean[i] * Wp[i * DD + d];
    hpp[b * DD + d] = acc;
}

// ---------------- readout ----------------------------------------------------
__global__ void readout_kernel(const float* __restrict__ h, const float* __restrict__ hpp,
                               const float* __restrict__ Wr, const float* __restrict__ br,
                               float* __restrict__ out)
{
    __shared__ float WrS[2 * DD * OUTD];
    __shared__ float brS[OUTD];
    int tid = threadIdx.x;
    for (int i = tid; i < 2 * DD * OUTD; i += 128) WrS[i] = Wr[i];
    if (tid < OUTD) brS[tid] = br[tid];
    __syncthreads();

    int row = blockIdx.x * 128 + tid;
    int b = row >> 9;
    float a0 = brS[0], a1 = brS[1], a2 = brS[2];
    const float* hp = hpp + b * DD;
#pragma unroll 4
    for (int i = 0; i < DD; i++){
        float f = fmaxf(hp[i], 0.f);
        a0 += f * WrS[i * 3 + 0]; a1 += f * WrS[i * 3 + 1]; a2 += f * WrS[i * 3 + 2];
    }
    const float* hr = h + (size_t)row * DD;
#pragma unroll 4
    for (int i = 0; i < DD; i++){
        float f = fmaxf(hr[i], 0.f);
        a0 += f * WrS[(DD + i) * 3 + 0];
        a1 += f * WrS[(DD + i) * 3 + 1];
        a2 += f * WrS[(DD + i) * 3 + 2];
    }
    out[row * 3 + 0] = a0; out[row * 3 + 1] = a1; out[row * 3 + 2] = a2;
}

// ---------------- host launcher ----------------------------------------------
extern "C" void kernel_launch(void* const* d_in, const int* in_sizes, int n_in,
                              void* d_out, int out_size)
{
    const float* x    = (const float*)d_in[0];
    const int*   mask = (const int*)  d_in[1];
    const float* We   = (const float*)d_in[2];
    const float* Wq   = (const float*)d_in[3];
    const float* Wk   = (const float*)d_in[4];
    const float* Wv   = (const float*)d_in[5];
    const float* Wout = (const float*)d_in[6];
    const float* Wff1 = (const float*)d_in[7];
    const float* bff1 = (const float*)d_in[8];
    const float* Wff2 = (const float*)d_in[9];
    const float* bff2 = (const float*)d_in[10];
    const float* Wp   = (const float*)d_in[11];
    const float* Wr   = (const float*)d_in[12];
    const float* br   = (const float*)d_in[13];
    float* out = (float*)d_out;

    float *h, *qkv, *heads, *ff, *wt, *hpp;
    unsigned* mp;
    cudaGetSymbolAddress((void**)&h,     g_h);
    cudaGetSymbolAddress((void**)&qkv,   g_qkv);
    cudaGetSymbolAddress((void**)&heads, g_heads);
    cudaGetSymbolAddress((void**)&ff,    g_ff);
    cudaGetSymbolAddress((void**)&wt,    g_wt);
    cudaGetSymbolAddress((void**)&hpp,   g_hpp);
    cudaGetSymbolAddress((void**)&mp,    g_mpack);

    cudaFuncSetAttribute(attn_mma,
                         cudaFuncAttributeMaxDynamicSharedMemorySize, ATTN_SMEM);

    repack_kernel<<<(LYR*DD*QKVN + 255) / 256, 256>>>(Wq, Wk, Wv, wt);
    maskpack_kernel<<<(BB*NN*(NN/32) + 255) / 256, 256>>>(mask, mp);

    // embed: h = relu(x @ We)
    gemm_tf32<<<dim3(DD / 64, ROWS / 128), 256>>>(
        x, We, nullptr, nullptr, h, ROWS, FIN, DD, 1);

    for (int l = 0; l < LYR; l++){
        // fused QKV
        gemm_tf32<<<dim3(QKVN / 64, ROWS / 128), 256>>>(
            h, wt + (size_t)l * DD * QKVN, nullptr, nullptr, qkv,
            ROWS, DD, QKVN, 0);

        // attention
        attn_mma<<<BB * HH, 256, ATTN_SMEM>>>(qkv, mp, heads);

        // h = h + heads @ Wout[l]
        gemm_tf32<<<dim3(DD / 64, ROWS / 128), 256>>>(
            heads, Wout + (size_t)l * HH * DKK * DD, nullptr, h, h,
            ROWS, DD, DD, 0);

        // ff = relu(h @ Wff1 + bff1)
        gemm_tf32<<<dim3(FF / 64, ROWS / 128), 256>>>(
            h, Wff1 + (size_t)l * DD * FF, bff1 + (size_t)l * FF, nullptr, ff,
            ROWS, DD, FF, 1);

        // h = h + ff @ Wff2 + bff2
        gemm_tf32<<<dim3(DD / 64, ROWS / 128), 256>>>(
            ff, Wff2 + (size_t)l * FF * DD, bff2 + (size_t)l * DD, h, h,
            ROWS, FF, DD, 0);
    }

    pool_kernel<<<BB, DD>>>(h, Wp, hpp);
    readout_kernel<<<ROWS / 128, 128>>>(h, hpp, Wr, br, out);
}

// round 3
// speedup vs baseline: 2.8073x; 1.3234x over previous
#include <cuda_runtime.h>
#include <cuda_bf16.h>
#include <math.h>
#include <stdint.h>

// Problem dims
#define LYR 3
#define HH  8
#define DD  128
#define DKK 16
#define FF  512
#define BB  32
#define NN  512
#define FIN 16
#define OUTD 3
#define ROWS (BB*NN)          // 16384
#define QKVN (3*DD)           // 384
#define SCL (0.25f * 1.44269504089f)
#define MASKVAL (-2e30f)
#define MINIT   (-1e30f)

// ---------------- scratch (__device__ globals; no allocation) ----------------
__device__ float    g_h[ROWS*DD];        // exact trunk
__device__ float    g_hr[ROWS*DD];       // tf32-rounded trunk (GEMM A input)
__device__ float    g_qkv[ROWS*QKVN];    // rounded
__device__ float    g_heads[ROWS*DD];    // rounded
__device__ float    g_ff[ROWS*FF];       // rounded
__device__ float    g_xr[ROWS*FIN];      // rounded x
__device__ float    g_hpp[BB*DD];
__device__ unsigned g_mpack[BB*NN*(NN/32)];
// transposed + rounded weights [N][K]
__device__ float    g_weT[DD*FIN];
__device__ float    g_wqkvT[LYR*QKVN*DD];
__device__ float    g_woutT[LYR*DD*DD];
__device__ float    g_wff1T[LYR*FF*DD];
__device__ float    g_wff2T[LYR*DD*FF];

// ---------------- helpers ----------------------------------------------------
__device__ __forceinline__ uint32_t f2u(float x){ return __float_as_uint(x); }
__device__ __forceinline__ float cvt_tf32(float x){
    uint32_t u; asm("cvt.rna.tf32.f32 %0, %1;" : "=r"(u) : "f"(x));
    return __uint_as_float(u);
}
__device__ __forceinline__ uint32_t bf16x2(float hi, float lo){
    uint32_t r; asm("cvt.rn.bf16x2.f32 %0, %1, %2;" : "=r"(r) : "f"(hi), "f"(lo));
    return r;
}
__device__ __forceinline__ uint32_t smem_u32(const void* p){
    uint32_t a;
    asm("{ .reg .u64 t; cvta.to.shared.u64 t, %1; cvt.u32.u64 %0, t; }" : "=r"(a) : "l"(p));
    return a;
}
__device__ __forceinline__ void cpa16(uint32_t s, const void* g){
    asm volatile("cp.async.cg.shared.global [%0], [%1], 16;" :: "r"(s), "l"(g) : "memory");
}
__device__ __forceinline__ void ldsm4(uint32_t& r0, uint32_t& r1, uint32_t& r2, uint32_t& r3,
                                      uint32_t addr){
    asm volatile("ldmatrix.sync.aligned.m8n8.x4.shared.b16 {%0,%1,%2,%3}, [%4];"
                 : "=r"(r0), "=r"(r1), "=r"(r2), "=r"(r3) : "r"(addr));
}
__device__ __forceinline__ void mma_tf32(float c[4], const uint32_t a[4],
                                         uint32_t b0, uint32_t b1){
    asm volatile("mma.sync.aligned.m16n8k8.row.col.f32.tf32.tf32.f32 "
        "{%0,%1,%2,%3},{%4,%5,%6,%7},{%8,%9},{%0,%1,%2,%3};\n"
        : "+f"(c[0]),"+f"(c[1]),"+f"(c[2]),"+f"(c[3])
        : "r"(a[0]),"r"(a[1]),"r"(a[2]),"r"(a[3]),"r"(b0),"r"(b1));
}
__device__ __forceinline__ void mma_bf16(float c[4], const uint32_t a[4], uint32_t b0, uint32_t b1){
    asm volatile("mma.sync.aligned.m16n8k16.row.col.f32.bf16.bf16.f32 "
        "{%0,%1,%2,%3},{%4,%5,%6,%7},{%8,%9},{%0,%1,%2,%3};\n"
        : "+f"(c[0]),"+f"(c[1]),"+f"(c[2]),"+f"(c[3])
        : "r"(a[0]),"r"(a[1]),"r"(a[2]),"r"(a[3]),"r"(b0),"r"(b1));
}

// ---------------- prep kernels ------------------------------------------------
__global__ void round_kernel(const float* __restrict__ src, float* __restrict__ dst, int n){
    int i = blockIdx.x * 256 + threadIdx.x;
    if (i < n) dst[i] = cvt_tf32(src[i]);
}
// src [b][R][C] -> dst [b][C][R], rounded
__global__ void trt_kernel(const float* __restrict__ src, float* __restrict__ dst,
                           int R, int C, int total){
    int idx = blockIdx.x * 256 + threadIdx.x;
    if (idx >= total) return;
    int rc = R * C;
    int b = idx / rc, rem = idx % rc;
    int cc = rem / R, rr = rem % R;
    dst[idx] = cvt_tf32(src[(size_t)b * rc + rr * C + cc]);
}
// Wq/Wk/Wv [L,H,D,DK] -> [L][384][128] rounded (row = out col, col = d)
__global__ void repack_qkvT(const float* __restrict__ Wq, const float* __restrict__ Wk,
                            const float* __restrict__ Wv, float* __restrict__ dst){
    int idx = blockIdx.x * 256 + threadIdx.x;
    if (idx >= LYR*QKVN*DD) return;
    int l = idx / (QKVN*DD), rem = idx % (QKVN*DD);
    int n = rem / DD, d = rem % DD;
    int sel = n >> 7, hc = n & 127, h = hc >> 4, kk = hc & 15;
    const float* W = (sel == 0) ? Wq : (sel == 1) ? Wk : Wv;
    dst[idx] = cvt_tf32(W[(((l*HH + h)*DD) + d)*DKK + kk]);
}
__global__ void maskpack_kernel(const int* __restrict__ mask, unsigned* __restrict__ mpack){
    int idx = blockIdx.x * 256 + threadIdx.x;
    if (idx >= BB*NN*(NN/32)) return;
    const int* src = mask + (size_t)idx * 32;
    unsigned v = 0;
#pragma unroll
    for (int j = 0; j < 32; j += 4){
        int4 mm = *(const int4*)(src + j);
        v |= ((unsigned)(mm.x != 0)) << (j    );
        v |= ((unsigned)(mm.y != 0)) << (j + 1);
        v |= ((unsigned)(mm.z != 0)) << (j + 2);
        v |= ((unsigned)(mm.w != 0)) << (j + 3);
    }
    mpack[idx] = v;
}

// ---------------- pipelined tf32 tensor GEMM ---------------------------------
// A [M,K] rowmajor (pre-rounded), Bt [N,K] rowmajor (pre-rounded).
// BM=128 BN=64, 8 warps (4m x 2n), cp.async 3-stage, LDSM fragments.
// C (exact) and/or Cr (tf32-rounded) outputs; res/bias/relu optional.
template<int BK>
__global__ __launch_bounds__(256)
void gemm_tc(const float* __restrict__ A, const float* __restrict__ Bt,
             const float* __restrict__ bias, const float* __restrict__ res,
             float* __restrict__ C, float* __restrict__ Cr,
             int M, int K, int N, int do_relu)
{
    constexpr int BM = 128, BN = 64, S = 3;
    constexpr int CH = BK / 4, CM = CH - 1;     // 16B chunks per row
    constexpr int BKB = BK * 4;                 // row bytes
    constexpr int ABYTES = BM * BKB, BBYTES = BN * BKB;
    constexpr int STAGE = ABYTES + BBYTES;
    constexpr int ACH = BM * CH, BCH = BN * CH;

    extern __shared__ char smraw[];
    const uint32_t smbase = smem_u32(smraw);

    const int tid = threadIdx.x, lane = tid & 31, wid = tid >> 5;
    const int wm = wid >> 1, wn = wid & 1;
    const int brow = blockIdx.y * BM, bcol = blockIdx.x * BN;
    const int ntile = K / BK;

    float c[2][4][4];
#pragma unroll
    for (int mt = 0; mt < 2; mt++)
#pragma unroll
        for (int nt = 0; nt < 4; nt++)
#pragma unroll
            for (int i = 0; i < 4; i++) c[mt][nt][i] = 0.f;

    // ---- prologue: issue stages 0..S-2 ----
#pragma unroll
    for (int s = 0; s < S - 1; s++){
        if (s < ntile){
            uint32_t sb = smbase + s * STAGE;
#pragma unroll
            for (int j = 0; j < ACH/256; j++){
                int id = tid + j * 256, r = id / CH, cc = id & CM;
                cpa16(sb + r * BKB + (((cc ^ (r & CM))) << 4),
                      A + (size_t)(brow + r) * K + s * BK + cc * 4);
            }
#pragma unroll
            for (int j = 0; j < BCH/256; j++){
                int id = tid + j * 256, r = id / CH, cc = id & CM;
                cpa16(sb + ABYTES + r * BKB + (((cc ^ (r & CM))) << 4),
                      Bt + (size_t)(bcol + r) * K + s * BK + cc * 4);
            }
        }
        asm volatile("cp.async.commit_group;" ::: "memory");
    }

    // fragment row constants
    int arow0 = wm * 32 + (lane & 15);
    const int ahi = (lane >> 4);
    const int bhi = (lane >> 3) & 1;
    const int brfrag = wn * 32 + (lane & 7) + ((lane >> 4) << 3);

    for (int t = 0; t < ntile; t++){
        asm volatile("cp.async.wait_group %0;" :: "n"(S - 2) : "memory");
        __syncthreads();

        // issue stage t+S-1
        {
            int tn = t + S - 1;
            if (tn < ntile){
                uint32_t sb = smbase + (tn % S) * STAGE;
#pragma unroll
                for (int j = 0; j < ACH/256; j++){
                    int id = tid + j * 256, r = id / CH, cc = id & CM;
                    cpa16(sb + r * BKB + (((cc ^ (r & CM))) << 4),
                          A + (size_t)(brow + r) * K + tn * BK + cc * 4);
                }
#pragma unroll
                for (int j = 0; j < BCH/256; j++){
                    int id = tid + j * 256, r = id / CH, cc = id & CM;
                    cpa16(sb + ABYTES + r * BKB + (((cc ^ (r & CM))) << 4),
                          Bt + (size_t)(bcol + r) * K + tn * BK + cc * 4);
                }
            }
            asm volatile("cp.async.commit_group;" ::: "memory");
        }

        // compute on stage t%S
        uint32_t sb = smbase + (t % S) * STAGE;
#pragma unroll
        for (int ks = 0; ks < BK/8; ks++){
            uint32_t af[2][4];
#pragma unroll
            for (int mt = 0; mt < 2; mt++){
                int r = arow0 + mt * 16;
                uint32_t ck = (uint32_t)(ks * 2 + ahi);
                ldsm4(af[mt][0], af[mt][1], af[mt][2], af[mt][3],
                      sb + r * BKB + (((ck ^ (uint32_t)(r & CM))) << 4));
            }
            uint32_t bf[2][4];
#pragma unroll
            for (int pr = 0; pr < 2; pr++){
                int r = brfrag + pr * 16;
                uint32_t ck = (uint32_t)(ks * 2 + bhi);
                ldsm4(bf[pr][0], bf[pr][1], bf[pr][2], bf[pr][3],
                      sb + ABYTES + r * BKB + (((ck ^ (uint32_t)(r & CM))) << 4));
            }
#pragma unroll
            for (int mt = 0; mt < 2; mt++)
#pragma unroll
                for (int pr = 0; pr < 2; pr++){
                    mma_tf32(c[mt][2*pr],     af[mt], bf[pr][0], bf[pr][1]);
                    mma_tf32(c[mt][2*pr + 1], af[mt], bf[pr][2], bf[pr][3]);
                }
        }
    }

    // ---- epilogue ----
#pragma unroll
    for (int mt = 0; mt < 2; mt++){
        int r0 = brow + wm * 32 + mt * 16 + (lane >> 2);
#pragma unroll
        for (int nt = 0; nt < 4; nt++){
            int col = bcol + wn * 32 + nt * 8 + (lane & 3) * 2;
            float2 bb = make_float2(0.f, 0.f);
            if (bias) bb = *(const float2*)(bias + col);
            size_t off0 = (size_t)r0 * N + col;
            size_t off1 = (size_t)(r0 + 8) * N + col;
            float2 v0 = make_float2(c[mt][nt][0] + bb.x, c[mt][nt][1] + bb.y);
            float2 v1 = make_float2(c[mt][nt][2] + bb.x, c[mt][nt][3] + bb.y);
            if (res){
                float2 r0v = *(const float2*)(res + off0);
                float2 r1v = *(const float2*)(res + off1);
                v0.x += r0v.x; v0.y += r0v.y; v1.x += r1v.x; v1.y += r1v.y;
            }
            if (do_relu){
                v0.x = fmaxf(v0.x, 0.f); v0.y = fmaxf(v0.y, 0.f);
                v1.x = fmaxf(v1.x, 0.f); v1.y = fmaxf(v1.y, 0.f);
            }
            if (C){
                *(float2*)(C + off0) = v0;
                *(float2*)(C + off1) = v1;
            }
            if (Cr){
                *(float2*)(Cr + off0) = make_float2(cvt_tf32(v0.x), cvt_tf32(v0.y));
                *(float2*)(Cr + off1) = make_float2(cvt_tf32(v1.x), cvt_tf32(v1.y));
            }
        }
    }
}

// ---------------- flash attention via MMA ------------------------------------
// CTA per (b,h), 8 warps. K tile [512][16] tf32 swizzled (LDSM b-frags);
// V bf16 transposed [16][520]. qkv is pre-rounded tf32.
#define KS_BYTES (NN*16*4)
#define ATTN_SMEM (KS_BYTES + DKK*520*2)

__global__ __launch_bounds__(256)
void attn_mma(const float* __restrict__ qkv, const unsigned* __restrict__ mpack,
              float* __restrict__ heads)
{
    extern __shared__ char smraw[];
    float* Ks = (float*)smraw;                               // [512][16] swizzled
    __nv_bfloat16* Vs = (__nv_bfloat16*)(smraw + KS_BYTES);  // [16][520]
    const uint32_t ksbase = smem_u32(smraw);

    const int b = blockIdx.x >> 3, h = blockIdx.x & 7;
    const int tid = threadIdx.x, lane = tid & 31, wid = tid >> 5;

    for (int i = tid; i < NN * 4; i += 256){
        int row = i >> 2, c = i & 3;
        const float* base = qkv + (size_t)(b * NN + row) * QKVN + h * DKK;
        float4 kk = *(const float4*)(base + DD + c * 4);
        *(float4*)&Ks[row * 16 + ((c ^ (row & 3)) << 2)] = kk;
        float4 vv = *(const float4*)(base + 2 * DD + c * 4);
        Vs[(c*4 + 0) * 520 + row] = __float2bfloat16(vv.x);
        Vs[(c*4 + 1) * 520 + row] = __float2bfloat16(vv.y);
        Vs[(c*4 + 2) * 520 + row] = __float2bfloat16(vv.z);
        Vs[(c*4 + 3) * 520 + row] = __float2bfloat16(vv.w);
    }
    __syncthreads();

    const float* Qb = qkv + (size_t)(b * NN) * QKVN + h * DKK;
    const int bfr = (lane & 7) + ((lane >> 4) << 3);
    const int bhi = (lane >> 3) & 1;

    for (int qb = 0; qb < 4; qb++){
        const int qrow = qb * 128 + wid * 16 + (lane >> 2);

        uint32_t aq[2][4];
#pragma unroll
        for (int ks = 0; ks < 2; ks++){
            int cc = ks * 8 + (lane & 3);
            aq[ks][0] = f2u(Qb[(size_t)qrow * QKVN + cc]);
            aq[ks][1] = f2u(Qb[(size_t)(qrow + 8) * QKVN + cc]);
            aq[ks][2] = f2u(Qb[(size_t)qrow * QKVN + cc + 4]);
            aq[ks][3] = f2u(Qb[(size_t)(qrow + 8) * QKVN + cc + 4]);
        }

        float m0 = MINIT, m1 = MINIT, l0 = 0.f, l1 = 0.f;
        float o[2][4];
#pragma unroll
        for (int vt = 0; vt < 2; vt++)
#pragma unroll
            for (int i = 0; i < 4; i++) o[vt][i] = 0.f;

        for (int kb = 0; kb < 8; kb++){
            float s[8][4];
#pragma unroll
            for (int nt = 0; nt < 8; nt++)
                s[nt][0] = s[nt][1] = s[nt][2] = s[nt][3] = 0.f;
#pragma unroll
            for (int ks = 0; ks < 2; ks++){
#pragma unroll
                for (int pr = 0; pr < 4; pr++){
                    int rn = kb * 64 + pr * 16 + bfr;
                    uint32_t ck = (uint32_t)(ks * 2 + bhi);
                    uint32_t b0, b1, b2, b3;
                    ldsm4(b0, b1, b2, b3,
                          ksbase + rn * 64 + (((ck ^ (uint32_t)(rn & 3))) << 4));
                    mma_tf32(s[2*pr],     aq[ks], b0, b1);
                    mma_tf32(s[2*pr + 1], aq[ks], b2, b3);
                }
            }
            // mask + scale
            const unsigned* mpr = mpack + ((size_t)(b * NN + qrow) << 4) + kb * 2;
            unsigned mw00 = mpr[0], mw01 = mpr[1];
            unsigned mw10 = mpr[8 * 16], mw11 = mpr[8 * 16 + 1];
#pragma unroll
            for (int nt = 0; nt < 8; nt++){
                int cb = nt * 8 + (lane & 3) * 2;
                unsigned wlo = (cb & 32) ? mw01 : mw00;
                unsigned whi = (cb & 32) ? mw11 : mw10;
                int bit = cb & 31;
                s[nt][0] = ((wlo >> bit)       & 1) ? s[nt][0] * SCL : MASKVAL;
                s[nt][1] = ((wlo >> (bit + 1)) & 1) ? s[nt][1] * SCL : MASKVAL;
                s[nt][2] = ((whi >> bit)       & 1) ? s[nt][2] * SCL : MASKVAL;
                s[nt][3] = ((whi >> (bit + 1)) & 1) ? s[nt][3] * SCL : MASKVAL;
            }
            // online softmax (log2 domain)
            float rx0 = MASKVAL, rx1 = MASKVAL;
#pragma unroll
            for (int nt = 0; nt < 8; nt++){
                rx0 = fmaxf(rx0, fmaxf(s[nt][0], s[nt][1]));
                rx1 = fmaxf(rx1, fmaxf(s[nt][2], s[nt][3]));
            }
            rx0 = fmaxf(rx0, __shfl_xor_sync(0xffffffffu, rx0, 1));
            rx0 = fmaxf(rx0, __shfl_xor_sync(0xffffffffu, rx0, 2));
            rx1 = fmaxf(rx1, __shfl_xor_sync(0xffffffffu, rx1, 1));
            rx1 = fmaxf(rx1, __shfl_xor_sync(0xffffffffu, rx1, 2));
            float nm0 = fmaxf(m0, rx0), nm1 = fmaxf(m1, rx1);
            float f0 = exp2f(m0 - nm0), f1 = exp2f(m1 - nm1);
            m0 = nm0; m1 = nm1;
            l0 *= f0;  l1 *= f1;
#pragma unroll
            for (int vt = 0; vt < 2; vt++){
                o[vt][0] *= f0; o[vt][1] *= f0;
                o[vt][2] *= f1; o[vt][3] *= f1;
            }
#pragma unroll
            for (int nt = 0; nt < 8; nt++){
                s[nt][0] = exp2f(s[nt][0] - m0);
                s[nt][1] = exp2f(s[nt][1] - m0);
                s[nt][2] = exp2f(s[nt][2] - m1);
                s[nt][3] = exp2f(s[nt][3] - m1);
                l0 += s[nt][0] + s[nt][1];
                l1 += s[nt][2] + s[nt][3];
            }
            // P @ V
#pragma unroll
            for (int kt = 0; kt < 4; kt++){
                uint32_t pa[4];
                pa[0] = bf16x2(s[2 * kt][1],     s[2 * kt][0]);
                pa[1] = bf16x2(s[2 * kt][3],     s[2 * kt][2]);
                pa[2] = bf16x2(s[2 * kt + 1][1], s[2 * kt + 1][0]);
                pa[3] = bf16x2(s[2 * kt + 1][3], s[2 * kt + 1][2]);
#pragma unroll
                for (int vt = 0; vt < 2; vt++){
                    int dk = vt * 8 + (lane >> 2);
                    int kv = kb * 64 + kt * 16 + (lane & 3) * 2;
                    uint32_t b0 = *(const uint32_t*)&Vs[dk * 520 + kv];
                    uint32_t b1 = *(const uint32_t*)&Vs[dk * 520 + kv + 8];
                    mma_bf16(o[vt], pa, b0, b1);
                }
            }
        }

        l0 += __shfl_xor_sync(0xffffffffu, l0, 1);
        l0 += __shfl_xor_sync(0xffffffffu, l0, 2);
        l1 += __shfl_xor_sync(0xffffffffu, l1, 1);
        l1 += __shfl_xor_sync(0xffffffffu, l1, 2);
        float i0 = 1.f / l0, i1 = 1.f / l1;
#pragma unroll
        for (int vt = 0; vt < 2; vt++){
            int col = h * DKK + vt * 8 + (lane & 3) * 2;
            float2 v0 = make_float2(cvt_tf32(o[vt][0] * i0), cvt_tf32(o[vt][1] * i0));
            float2 v1 = make_float2(cvt_tf32(o[vt][2] * i1), cvt_tf32(o[vt][3] * i1));
            *(float2*)&heads[(size_t)(b * NN + qrow) * DD + col]     = v0;
            *(float2*)&heads[(size_t)(b * NN + qrow + 8) * DD + col] = v1;
        }
    }
}

// ---------------- pooling + Wp ------------------------------------------------
__global__ void pool_kernel(const float* __restrict__ h, const float* __restrict__ Wp,
                            float* __restrict__ hpp)
{
    __shared__ float mean[DD];
    int b = blockIdx.x, d = threadIdx.x;
    const float* hp = h + (size_t)b * NN * DD + d;
    float s = 0.f;
    for (int n = 0; n < NN; n++) s += hp[(size_t)n * DD];
    mean[d] = s * (1.f / (float)NN);
    __syncthreads();
    float acc = 0.f;
#pragma unroll 4
    for (int i = 0; i < DD; i++) acc += mean[i] * Wp[i * DD + d];
    hpp[b * DD + d] = acc;
}

// ---------------- readout ----------------------------------------------------
__global__ void readout_kernel(const float* __restrict__ h, const float* __restrict__ hpp,
                               const float* __restrict__ Wr, const float* __restrict__ br,
                               float* __restrict__ out)
{
    __shared__ float WrS[2 * DD * OUTD];
    __shared__ float brS[OUTD];
    int tid = threadIdx.x;
    for (int i = tid; i < 2 * DD * OUTD; i += 128) WrS[i] = Wr[i];
    if (tid < OUTD) brS[tid] = br[tid];
    __syncthreads();

    int row = blockIdx.x * 128 + tid;
    int b = row >> 9;
    float a0 = brS[0], a1 = brS[1], a2 = brS[2];
    const float* hp = hpp + b * DD;
#pragma unroll 4
    for (int i = 0; i < DD; i++){
        float f = fmaxf(hp[i], 0.f);
        a0 += f * WrS[i * 3 + 0]; a1 += f * WrS[i * 3 + 1]; a2 += f * WrS[i * 3 + 2];
    }
    const float* hr = h + (size_t)row * DD;
#pragma unroll 4
    for (int i = 0; i < DD; i++){
        float f = fmaxf(hr[i], 0.f);
        a0 += f * WrS[(DD + i) * 3 + 0];
        a1 += f * WrS[(DD + i) * 3 + 1];
        a2 += f * WrS[(DD + i) * 3 + 2];
    }
    out[row * 3 + 0] = a0; out[row * 3 + 1] = a1; out[row * 3 + 2] = a2;
}

// ---------------- host launcher ----------------------------------------------
extern "C" void kernel_launch(void* const* d_in, const int* in_sizes, int n_in,
                              void* d_out, int out_size)
{
    const float* x    = (const float*)d_in[0];
    const int*   mask = (const int*)  d_in[1];
    const float* We   = (const float*)d_in[2];
    const float* Wq   = (const float*)d_in[3];
    const float* Wk   = (const float*)d_in[4];
    const float* Wv   = (const float*)d_in[5];
    const float* Wout = (const float*)d_in[6];
    const float* Wff1 = (const float*)d_in[7];
    const float* bff1 = (const float*)d_in[8];
    const float* Wff2 = (const float*)d_in[9];
    const float* bff2 = (const float*)d_in[10];
    const float* Wp   = (const float*)d_in[11];
    const float* Wr   = (const float*)d_in[12];
    const float* br   = (const float*)d_in[13];
    float* out = (float*)d_out;

    float *h, *hr, *qkv, *heads, *ff, *xr, *hpp;
    float *weT, *wqkvT, *woutT, *wff1T, *wff2T;
    unsigned* mp;
    cudaGetSymbolAddress((void**)&h,     g_h);
    cudaGetSymbolAddress((void**)&hr,    g_hr);
    cudaGetSymbolAddress((void**)&qkv,   g_qkv);
    cudaGetSymbolAddress((void**)&heads, g_heads);
    cudaGetSymbolAddress((void**)&ff,    g_ff);
    cudaGetSymbolAddress((void**)&xr,    g_xr);
    cudaGetSymbolAddress((void**)&hpp,   g_hpp);
    cudaGetSymbolAddress((void**)&mp,    g_mpack);
    cudaGetSymbolAddress((void**)&weT,   g_weT);
    cudaGetSymbolAddress((void**)&wqkvT, g_wqkvT);
    cudaGetSymbolAddress((void**)&woutT, g_woutT);
    cudaGetSymbolAddress((void**)&wff1T, g_wff1T);
    cudaGetSymbolAddress((void**)&wff2T, g_wff2T);

    const int SM32 = 3 * (128*128 + 64*128);   // 73728
    const int SM16 = 3 * (128*64 + 64*64);     // 36864
    cudaFuncSetAttribute(gemm_tc<32>, cudaFuncAttributeMaxDynamicSharedMemorySize, SM32);
    cudaFuncSetAttribute(gemm_tc<16>, cudaFuncAttributeMaxDynamicSharedMemorySize, SM16);
    cudaFuncSetAttribute(attn_mma, cudaFuncAttributeMaxDynamicSharedMemorySize, ATTN_SMEM);

    // prep
    round_kernel<<<(ROWS*FIN + 255)/256, 256>>>(x, xr, ROWS*FIN);
    repack_qkvT<<<(LYR*QKVN*DD + 255)/256, 256>>>(Wq, Wk, Wv, wqkvT);
    trt_kernel<<<(FIN*DD + 255)/256, 256>>>(We, weT, FIN, DD, FIN*DD);
    trt_kernel<<<(LYR*DD*DD + 255)/256, 256>>>(Wout, woutT, DD, DD, LYR*DD*DD);
    trt_kernel<<<(LYR*DD*FF + 255)/256, 256>>>(Wff1, wff1T, DD, FF, LYR*DD*FF);
    trt_kernel<<<(LYR*FF*DD + 255)/256, 256>>>(Wff2, wff2T, FF, DD, LYR*FF*DD);
    maskpack_kernel<<<(BB*NN*(NN/32) + 255)/256, 256>>>(mask, mp);

    // embed: h = relu(x @ We), exact + rounded
    gemm_tc<16><<<dim3(DD/64, ROWS/128), 256, SM16>>>(
        xr, weT, nullptr, nullptr, h, hr, ROWS, FIN, DD, 1);

    for (int l = 0; l < LYR; l++){
        // fused QKV (rounded only)
        gemm_tc<32><<<dim3(QKVN/64, ROWS/128), 256, SM32>>>(
            hr, wqkvT + (size_t)l * QKVN * DD, nullptr, nullptr,
            nullptr, qkv, ROWS, DD, QKVN, 0);

        attn_mma<<<BB * HH, 256, ATTN_SMEM>>>(qkv, mp, heads);

        // h = h + heads @ Wout[l]  (exact + rounded)
        gemm_tc<32><<<dim3(DD/64, ROWS/128), 256, SM32>>>(
            heads, woutT + (size_t)l * DD * DD, nullptr, h,
            h, hr, ROWS, DD, DD, 0);

        // ff = relu(h @ Wff1 + bff1)  (rounded only)
        gemm_tc<32><<<dim3(FF/64, ROWS/128), 256, SM32>>>(
            hr, wff1T + (size_t)l * FF * DD, bff1 + (size_t)l * FF, nullptr,
            nullptr, ff, ROWS, DD, FF, 1);

        // h = h + ff @ Wff2 + bff2  (exact + rounded)
        gemm_tc<32><<<dim3(DD/64, ROWS/128), 256, SM32>>>(
            ff, wff2T + (size_t)l * DD * FF, bff2 + (size_t)l * DD, h,
            h, hr, ROWS, FF, DD, 0);
    }

    pool_kernel<<<BB, DD>>>(h, Wp, hpp);
    readout_kernel<<<ROWS/128, 128>>>(h, hpp, Wr, br, out);
}

// round 5
// speedup vs baseline: 3.5435x; 1.2622x over previous
#include <cuda_runtime.h>
#include <cuda_fp16.h>
#include <math.h>
#include <stdint.h>

// Problem dims
#define LYR 3
#define HH  8
#define DD  128
#define DKK 16
#define FF  512
#define BB  32
#define NN  512
#define FIN 16
#define OUTD 3
#define ROWS (BB*NN)          // 16384
#define QKVN (3*DD)           // 384
#define SCL (0.25f * 1.44269504089f)
#define MASKVAL (-2e30f)
#define MINIT   (-1e30f)

// ---------------- scratch (__device__ globals; no allocation) ----------------
__device__ __align__(16) float  g_h[ROWS*DD];       // exact fp32 trunk
__device__ __align__(16) __half g_hh[ROWS*DD];      // fp16 trunk copy (GEMM A)
__device__ __align__(16) __half g_qkv[ROWS*QKVN];
__device__ __align__(16) __half g_heads[ROWS*DD];
__device__ __align__(16) __half g_ff[ROWS*FF];
__device__ __align__(16) __half g_xh[ROWS*FIN];
__device__ __align__(16) float  g_hpp[BB*DD];
__device__ __align__(16) unsigned g_mpack[BB*NN*(NN/32)];
// transposed fp16 weights [N][K]
__device__ __align__(16) __half g_weT[DD*FIN];
__device__ __align__(16) __half g_wqkvT[LYR*QKVN*DD];
__device__ __align__(16) __half g_woutT[LYR*DD*DD];
__device__ __align__(16) __half g_wff1T[LYR*FF*DD];
__device__ __align__(16) __half g_wff2T[LYR*DD*FF];

// ---------------- helpers ----------------------------------------------------
__device__ __forceinline__ uint32_t smem_u32(const void* p){
    uint32_t a;
    asm("{ .reg .u64 t; cvta.to.shared.u64 t, %1; cvt.u32.u64 %0, t; }" : "=r"(a) : "l"(p));
    return a;
}
__device__ __forceinline__ void cpa16(uint32_t s, const void* g){
    asm volatile("cp.async.cg.shared.global [%0], [%1], 16;" :: "r"(s), "l"(g) : "memory");
}
__device__ __forceinline__ void ldsm4(uint32_t& r0, uint32_t& r1, uint32_t& r2, uint32_t& r3,
                                      uint32_t addr){
    asm volatile("ldmatrix.sync.aligned.m8n8.x4.shared.b16 {%0,%1,%2,%3}, [%4];"
                 : "=r"(r0), "=r"(r1), "=r"(r2), "=r"(r3) : "r"(addr));
}
__device__ __forceinline__ void mma_f16(float c[4], const uint32_t a[4],
                                        uint32_t b0, uint32_t b1){
    asm volatile("mma.sync.aligned.m16n8k16.row.col.f32.f16.f16.f32 "
        "{%0,%1,%2,%3},{%4,%5,%6,%7},{%8,%9},{%0,%1,%2,%3};\n"
        : "+f"(c[0]),"+f"(c[1]),"+f"(c[2]),"+f"(c[3])
        : "r"(a[0]),"r"(a[1]),"r"(a[2]),"r"(a[3]),"r"(b0),"r"(b1));
}
__device__ __forceinline__ uint32_t f16x2(float hi, float lo){
    uint32_t r; asm("cvt.rn.f16x2.f32 %0, %1, %2;" : "=r"(r) : "f"(hi), "f"(lo));
    return r;
}

// ---------------- prep kernels ------------------------------------------------
__global__ void tohalf_kernel(const float* __restrict__ src, __half* __restrict__ dst, int n){
    int i = blockIdx.x * 256 + threadIdx.x;
    if (i < n) dst[i] = __float2half_rn(src[i]);
}
// src [b][R][C] fp32 -> dst [b][C][R] fp16
__global__ void trt_kernel(const float* __restrict__ src, __half* __restrict__ dst,
                           int R, int C, int total){
    int idx = blockIdx.x * 256 + threadIdx.x;
    if (idx >= total) return;
    int rc = R * C;
    int b = idx / rc, rem = idx % rc;
    int cc = rem / R, rr = rem % R;
    dst[idx] = __float2half_rn(src[(size_t)b * rc + rr * C + cc]);
}
// Wq/Wk/Wv [L,H,D,DK] -> [L][384][128] fp16
__global__ void repack_qkvT(const float* __restrict__ Wq, const float* __restrict__ Wk,
                            const float* __restrict__ Wv, __half* __restrict__ dst){
    int idx = blockIdx.x * 256 + threadIdx.x;
    if (idx >= LYR*QKVN*DD) return;
    int l = idx / (QKVN*DD), rem = idx % (QKVN*DD);
    int n = rem / DD, d = rem % DD;
    int sel = n >> 7, hc = n & 127, h = hc >> 4, kk = hc & 15;
    const float* W = (sel == 0) ? Wq : (sel == 1) ? Wk : Wv;
    dst[idx] = __float2half_rn(W[(((l*HH + h)*DD) + d)*DKK + kk]);
}
__global__ void maskpack_kernel(const int* __restrict__ mask, unsigned* __restrict__ mpack){
    int idx = blockIdx.x * 256 + threadIdx.x;
    if (idx >= BB*NN*(NN/32)) return;
    const int* src = mask + (size_t)idx * 32;
    unsigned v = 0;
#pragma unroll
    for (int j = 0; j < 32; j += 4){
        int4 mm = *(const int4*)(src + j);
        v |= ((unsigned)(mm.x != 0)) << (j    );
        v |= ((unsigned)(mm.y != 0)) << (j + 1);
        v |= ((unsigned)(mm.z != 0)) << (j + 2);
        v |= ((unsigned)(mm.w != 0)) << (j + 3);
    }
    mpack[idx] = v;
}

// ---------------- pipelined fp16 tensor GEMM ---------------------------------
// A [M,K] rowmajor fp16, Bt [N,K] rowmajor fp16. BM=128 BN=64, 8 warps (4m x 2n),
// cp.async 3-stage, LDSM frags, mma m16n8k16.f32.f16.f16.f32.
// Padded smem rows (PB bytes) -> bank-conflict-free cp.async stores AND ldsm reads.
// Outputs: C (exact fp32, opt) and/or Ch (fp16 copy, opt); res/bias/relu optional.
template<int BK>
__global__ __launch_bounds__(256)
void gemm_hc(const __half* __restrict__ A, const __half* __restrict__ Bt,
             const float* __restrict__ bias, const float* __restrict__ res,
             float* __restrict__ C, __half* __restrict__ Ch,
             int M, int K, int N, int do_relu)
{
    constexpr int BM = 128, BN = 64, S = 3;
    constexpr int CH = BK / 8;          // 16B chunks per row
    constexpr int PB = BK * 2 + 16;     // padded row bytes
    constexpr int ABYTES = BM * PB, BBYTES = BN * PB;
    constexpr int STAGE = ABYTES + BBYTES;
    constexpr int ACH = BM * CH, BCH = BN * CH;
    constexpr int KS = BK / 16;

    extern __shared__ char smraw[];
    const uint32_t smbase = smem_u32(smraw);

    const int tid = threadIdx.x, lane = tid & 31, wid = tid >> 5;
    const int wm = wid >> 1, wn = wid & 1;
    const int brow = blockIdx.y * BM, bcol = blockIdx.x * BN;
    const int ntile = K / BK;

    float c[2][4][4];
#pragma unroll
    for (int mt = 0; mt < 2; mt++)
#pragma unroll
        for (int nt = 0; nt < 4; nt++)
#pragma unroll
            for (int i = 0; i < 4; i++) c[mt][nt][i] = 0.f;

#pragma unroll
    for (int s = 0; s < S - 1; s++){
        if (s < ntile){
            uint32_t sb = smbase + s * STAGE;
#pragma unroll
            for (int j = 0; j < (ACH + 255)/256; j++){
                int id = tid + j * 256;
                if ((ACH & 255) == 0 || id < ACH){
                    int r = id / CH, cc = id % CH;
                    cpa16(sb + r * PB + cc * 16,
                          A + (size_t)(brow + r) * K + s * BK + cc * 8);
                }
            }
#pragma unroll
            for (int j = 0; j < (BCH + 255)/256; j++){
                int id = tid + j * 256;
                if ((BCH & 255) == 0 || id < BCH){
                    int r = id / CH, cc = id % CH;
                    cpa16(sb + ABYTES + r * PB + cc * 16,
                          Bt + (size_t)(bcol + r) * K + s * BK + cc * 8);
                }
            }
        }
        asm volatile("cp.async.commit_group;" ::: "memory");
    }

    const int arow0 = wm * 32 + (lane & 15);
    const int ahi = lane >> 4;
    const int bhi = (lane >> 3) & 1;
    const int brfrag = wn * 32 + (lane & 7) + ((lane >> 4) << 3);

    for (int t = 0; t < ntile; t++){
        asm volatile("cp.async.wait_group %0;" :: "n"(S - 2) : "memory");
        __syncthreads();

        {
            int tn = t + S - 1;
            if (tn < ntile){
                uint32_t sb = smbase + (tn % S) * STAGE;
#pragma unroll
                for (int j = 0; j < (ACH + 255)/256; j++){
                    int id = tid + j * 256;
                    if ((ACH & 255) == 0 || id < ACH){
                        int r = id / CH, cc = id % CH;
                        cpa16(sb + r * PB + cc * 16,
                              A + (size_t)(brow + r) * K + tn * BK + cc * 8);
                    }
                }
#pragma unroll
                for (int j = 0; j < (BCH + 255)/256; j++){
                    int id = tid + j * 256;
                    if ((BCH & 255) == 0 || id < BCH){
                        int r = id / CH, cc = id % CH;
                        cpa16(sb + ABYTES + r * PB + cc * 16,
                              Bt + (size_t)(bcol + r) * K + tn * BK + cc * 8);
                    }
                }
            }
            asm volatile("cp.async.commit_group;" ::: "memory");
        }

        uint32_t sb = smbase + (t % S) * STAGE;
#pragma unroll
        for (int ks = 0; ks < KS; ks++){
            uint32_t af[2][4];
#pragma unroll
            for (int mt = 0; mt < 2; mt++){
                int r = arow0 + mt * 16;
                ldsm4(af[mt][0], af[mt][1], af[mt][2], af[mt][3],
                      sb + r * PB + (ks * 2 + ahi) * 16);
            }
            uint32_t bf[2][4];
#pragma unroll
            for (int pr = 0; pr < 2; pr++){
                int r = brfrag + pr * 16;
                ldsm4(bf[pr][0], bf[pr][1], bf[pr][2], bf[pr][3],
                      sb + ABYTES + r * PB + (ks * 2 + bhi) * 16);
            }
#pragma unroll
            for (int mt = 0; mt < 2; mt++)
#pragma unroll
                for (int pr = 0; pr < 2; pr++){
                    mma_f16(c[mt][2*pr],     af[mt], bf[pr][0], bf[pr][1]);
                    mma_f16(c[mt][2*pr + 1], af[mt], bf[pr][2], bf[pr][3]);
                }
        }
    }

    // ---- epilogue ----
#pragma unroll
    for (int mt = 0; mt < 2; mt++){
        int r0 = brow + wm * 32 + mt * 16 + (lane >> 2);
#pragma unroll
        for (int nt = 0; nt < 4; nt++){
            int col = bcol + wn * 32 + nt * 8 + (lane & 3) * 2;
            float2 bb = make_float2(0.f, 0.f);
            if (bias) bb = *(const float2*)(bias + col);
            size_t off0 = (size_t)r0 * N + col;
            size_t off1 = (size_t)(r0 + 8) * N + col;
            float2 v0 = make_float2(c[mt][nt][0] + bb.x, c[mt][nt][1] + bb.y);
            float2 v1 = make_float2(c[mt][nt][2] + bb.x, c[mt][nt][3] + bb.y);
            if (res){
                float2 r0v = *(const float2*)(res + off0);
                float2 r1v = *(const float2*)(res + off1);
                v0.x += r0v.x; v0.y += r0v.y; v1.x += r1v.x; v1.y += r1v.y;
            }
            if (do_relu){
                v0.x = fmaxf(v0.x, 0.f); v0.y = fmaxf(v0.y, 0.f);
                v1.x = fmaxf(v1.x, 0.f); v1.y = fmaxf(v1.y, 0.f);
            }
            if (C){
                *(float2*)(C + off0) = v0;
                *(float2*)(C + off1) = v1;
            }
            if (Ch){
                *(__half2*)(Ch + off0) = __floats2half2_rn(v0.x, v0.y);
                *(__half2*)(Ch + off1) = __floats2half2_rn(v1.x, v1.y);
            }
        }
    }
}

// ---------------- flash attention, all-fp16 MMA ------------------------------
// CTA per (b,h), 8 warps. K tile [512] rows x 48B (fp16, padded, LDSM);
// V fp16 transposed [16][520]. qkv fp16. S=Q K^T one k16 mma; P fp16; P@V fp16.
#define KS_BYTES (NN*48)
#define ATTN_SMEM (KS_BYTES + DKK*520*2)

__global__ __launch_bounds__(256)
void attn_mma(const __half* __restrict__ qkv, const unsigned* __restrict__ mpack,
              __half* __restrict__ heads)
{
    extern __shared__ char smraw[];
    __half* Vs = (__half*)(smraw + KS_BYTES);   // [16][520]
    const uint32_t ksbase = smem_u32(smraw);

    const int b = blockIdx.x >> 3, h = blockIdx.x & 7;
    const int tid = threadIdx.x, lane = tid & 31, wid = tid >> 5;

    // fill K (row r at r*48, two 16B chunks) and V transposed
    for (int i = tid; i < NN * 2; i += 256){
        int row = i >> 1, cc = i & 1;
        const __half* base = qkv + (size_t)(b * NN + row) * QKVN + h * DKK;
        uint4 kk = *(const uint4*)(base + DD + cc * 8);
        *(uint4*)(smraw + row * 48 + cc * 16) = kk;
        const __half* vsrc = base + 2 * DD + cc * 8;
#pragma unroll
        for (int j = 0; j < 8; j++)
            Vs[(cc * 8 + j) * 520 + row] = vsrc[j];
    }
    __syncthreads();

    const __half* Qb = qkv + (size_t)(b * NN) * QKVN + h * DKK;
    const int bfr = (lane & 7) + ((lane >> 4) << 3);
    const int bhi = (lane >> 3) & 1;

    for (int qb = 0; qb < 4; qb++){
        const int qrow = qb * 128 + wid * 16 + (lane >> 2);

        uint32_t aq[4];
        {
            const __half* q0 = Qb + (size_t)qrow * QKVN + (lane & 3) * 2;
            const __half* q1 = Qb + (size_t)(qrow + 8) * QKVN + (lane & 3) * 2;
            aq[0] = *(const uint32_t*)q0;
            aq[1] = *(const uint32_t*)q1;
            aq[2] = *(const uint32_t*)(q0 + 8);
            aq[3] = *(const uint32_t*)(q1 + 8);
        }

        float m0 = MINIT, m1 = MINIT, l0 = 0.f, l1 = 0.f;
        float o[2][4];
#pragma unroll
        for (int vt = 0; vt < 2; vt++)
#pragma unroll
            for (int i = 0; i < 4; i++) o[vt][i] = 0.f;

        for (int kb = 0; kb < 8; kb++){
            float s[8][4];
#pragma unroll
            for (int nt = 0; nt < 8; nt++)
                s[nt][0] = s[nt][1] = s[nt][2] = s[nt][3] = 0.f;
#pragma unroll
            for (int pr = 0; pr < 4; pr++){
                int rn = kb * 64 + pr * 16 + bfr;
                uint32_t b0, b1, b2, b3;
                ldsm4(b0, b1, b2, b3, ksbase + rn * 48 + bhi * 16);
                mma_f16(s[2*pr],     aq, b0, b1);
                mma_f16(s[2*pr + 1], aq, b2, b3);
            }
            // mask + scale
            const unsigned* mpr = mpack + ((size_t)(b * NN + qrow) << 4) + kb * 2;
            unsigned mw00 = mpr[0], mw01 = mpr[1];
            unsigned mw10 = mpr[8 * 16], mw11 = mpr[8 * 16 + 1];
#pragma unroll
            for (int nt = 0; nt < 8; nt++){
                int cb = nt * 8 + (lane & 3) * 2;
                unsigned wlo = (cb & 32) ? mw01 : mw00;
                unsigned whi = (cb & 32) ? mw11 : mw10;
                int bit = cb & 31;
                s[nt][0] = ((wlo >> bit)       & 1) ? s[nt][0] * SCL : MASKVAL;
                s[nt][1] = ((wlo >> (bit + 1)) & 1) ? s[nt][1] * SCL : MASKVAL;
                s[nt][2] = ((whi >> bit)       & 1) ? s[nt][2] * SCL : MASKVAL;
                s[nt][3] = ((whi >> (bit + 1)) & 1) ? s[nt][3] * SCL : MASKVAL;
            }
            // online softmax (log2 domain)
            float rx0 = MASKVAL, rx1 = MASKVAL;
#pragma unroll
            for (int nt = 0; nt < 8; nt++){
                rx0 = fmaxf(rx0, fmaxf(s[nt][0], s[nt][1]));
                rx1 = fmaxf(rx1, fmaxf(s[nt][2], s[nt][3]));
            }
            rx0 = fmaxf(rx0, __shfl_xor_sync(0xffffffffu, rx0, 1));
            rx0 = fmaxf(rx0, __shfl_xor_sync(0xffffffffu, rx0, 2));
            rx1 = fmaxf(rx1, __shfl_xor_sync(0xffffffffu, rx1, 1));
            rx1 = fmaxf(rx1, __shfl_xor_sync(0xffffffffu, rx1, 2));
            float nm0 = fmaxf(m0, rx0), nm1 = fmaxf(m1, rx1);
            float f0 = exp2f(m0 - nm0), f1 = exp2f(m1 - nm1);
            m0 = nm0; m1 = nm1;
            l0 *= f0;  l1 *= f1;
#pragma unroll
            for (int vt = 0; vt < 2; vt++){
                o[vt][0] *= f0; o[vt][1] *= f0;
                o[vt][2] *= f1; o[vt][3] *= f1;
            }
#pragma unroll
            for (int nt = 0; nt < 8; nt++){
                s[nt][0] = exp2f(s[nt][0] - m0);
                s[nt][1] = exp2f(s[nt][1] - m0);
                s[nt][2] = exp2f(s[nt][2] - m1);
                s[nt][3] = exp2f(s[nt][3] - m1);
                l0 += s[nt][0] + s[nt][1];
                l1 += s[nt][2] + s[nt][3];
            }
            // P @ V (fp16)
#pragma unroll
            for (int kt = 0; kt < 4; kt++){
                uint32_t pa[4];
                pa[0] = f16x2(s[2 * kt][1],     s[2 * kt][0]);
                pa[1] = f16x2(s[2 * kt][3],     s[2 * kt][2]);
                pa[2] = f16x2(s[2 * kt + 1][1], s[2 * kt + 1][0]);
                pa[3] = f16x2(s[2 * kt + 1][3], s[2 * kt + 1][2]);
#pragma unroll
                for (int vt = 0; vt < 2; vt++){
                    int dk = vt * 8 + (lane >> 2);
                    int kv = kb * 64 + kt * 16 + (lane & 3) * 2;
                    uint32_t b0 = *(const uint32_t*)&Vs[dk * 520 + kv];
                    uint32_t b1 = *(const uint32_t*)&Vs[dk * 520 + kv + 8];
                    mma_f16(o[vt], pa, b0, b1);
                }
            }
        }

        l0 += __shfl_xor_sync(0xffffffffu, l0, 1);
        l0 += __shfl_xor_sync(0xffffffffu, l0, 2);
        l1 += __shfl_xor_sync(0xffffffffu, l1, 1);
        l1 += __shfl_xor_sync(0xffffffffu, l1, 2);
        float i0 = 1.f / l0, i1 = 1.f / l1;
#pragma unroll
        for (int vt = 0; vt < 2; vt++){
            int col = h * DKK + vt * 8 + (lane & 3) * 2;
            *(__half2*)&heads[(size_t)(b * NN + qrow) * DD + col] =
                __floats2half2_rn(o[vt][0] * i0, o[vt][1] * i0);
            *(__half2*)&heads[(size_t)(b * NN + qrow + 8) * DD + col] =
                __floats2half2_rn(o[vt][2] * i1, o[vt][3] * i1);
        }
    }
}

// ---------------- pooling + Wp ------------------------------------------------
__global__ void pool_kernel(const float* __restrict__ h, const float* __restrict__ Wp,
                            float* __restrict__ hpp)
{
    __shared__ float mean[DD];
    int b = blockIdx.x, d = threadIdx.x;
    const float* hp = h + (size_t)b * NN * DD + d;
    float s = 0.f;
    for (int n = 0; n < NN; n++) s += hp[(size_t)n * DD];
    mean[d] = s * (1.f / (float)NN);
    __syncthreads();
    float acc = 0.f;
#pragma unroll 4
    for (int i = 0; i < DD; i++) acc += mean[i] * Wp[i * DD + d];
    hpp[b * DD + d] = acc;
}

// ---------------- readout ----------------------------------------------------
__global__ void readout_kernel(const float* __restrict__ h, const float* __restrict__ hpp,
                               const float* __restrict__ Wr, const float* __restrict__ br,
                               float* __restrict__ out)
{
    __shared__ float WrS[2 * DD * OUTD];
    __shared__ float brS[OUTD];
    int tid = threadIdx.x;
    for (int i = tid; i < 2 * DD * OUTD; i += 128) WrS[i] = Wr[i];
    if (tid < OUTD) brS[tid] = br[tid];
    __syncthreads();

    int row = blockIdx.x * 128 + tid;
    int b = row >> 9;
    float a0 = brS[0], a1 = brS[1], a2 = brS[2];
    const float* hp = hpp + b * DD;
#pragma unroll 4
    for (int i = 0; i < DD; i++){
        float f = fmaxf(hp[i], 0.f);
        a0 += f * WrS[i * 3 + 0]; a1 += f * WrS[i * 3 + 1]; a2 += f * WrS[i * 3 + 2];
    }
    const float* hr = h + (size_t)row * DD;
#pragma unroll 4
    for (int i = 0; i < DD; i++){
        float f = fmaxf(hr[i], 0.f);
        a0 += f * WrS[(DD + i) * 3 + 0];
        a1 += f * WrS[(DD + i) * 3 + 1];
        a2 += f * WrS[(DD + i) * 3 + 2];
    }
    out[row * 3 + 0] = a0; out[row * 3 + 1] = a1; out[row * 3 + 2] = a2;
}

// ---------------- host launcher ----------------------------------------------
extern "C" void kernel_launch(void* const* d_in, const int* in_sizes, int n_in,
                              void* d_out, int out_size)
{
    const float* x    = (const float*)d_in[0];
    const int*   mask = (const int*)  d_in[1];
    const float* We   = (const float*)d_in[2];
    const float* Wq   = (const float*)d_in[3];
    const float* Wk   = (const float*)d_in[4];
    const float* Wv   = (const float*)d_in[5];
    const float* Wout = (const float*)d_in[6];
    const float* Wff1 = (const float*)d_in[7];
    const float* bff1 = (const float*)d_in[8];
    const float* Wff2 = (const float*)d_in[9];
    const float* bff2 = (const float*)d_in[10];
    const float* Wp   = (const float*)d_in[11];
    const float* Wr   = (const float*)d_in[12];
    const float* br   = (const float*)d_in[13];
    float* out = (float*)d_out;

    float *h, *hpp;
    __half *hh, *qkv, *heads, *ff, *xh, *weT, *wqkvT, *woutT, *wff1T, *wff2T;
    unsigned* mp;
    cudaGetSymbolAddress((void**)&h,     g_h);
    cudaGetSymbolAddress((void**)&hh,    g_hh);
    cudaGetSymbolAddress((void**)&qkv,   g_qkv);
    cudaGetSymbolAddress((void**)&heads, g_heads);
    cudaGetSymbolAddress((void**)&ff,    g_ff);
    cudaGetSymbolAddress((void**)&xh,    g_xh);
    cudaGetSymbolAddress((void**)&hpp,   g_hpp);
    cudaGetSymbolAddress((void**)&mp,    g_mpack);
    cudaGetSymbolAddress((void**)&weT,   g_weT);
    cudaGetSymbolAddress((void**)&wqkvT, g_wqkvT);
    cudaGetSymbolAddress((void**)&woutT, g_woutT);
    cudaGetSymbolAddress((void**)&wff1T, g_wff1T);
    cudaGetSymbolAddress((void**)&wff2T, g_wff2T);

    const int SM32 = 3 * (128*80 + 64*80);   // 46080
    const int SM16 = 3 * (128*48 + 64*48);   // 27648
    cudaFuncSetAttribute(gemm_hc<32>, cudaFuncAttributeMaxDynamicSharedMemorySize, SM32);
    cudaFuncSetAttribute(gemm_hc<16>, cudaFuncAttributeMaxDynamicSharedMemorySize, SM16);
    cudaFuncSetAttribute(attn_mma, cudaFuncAttributeMaxDynamicSharedMemorySize, ATTN_SMEM);

    // prep
    tohalf_kernel<<<(ROWS*FIN + 255)/256, 256>>>(x, xh, ROWS*FIN);
    repack_qkvT<<<(LYR*QKVN*DD + 255)/256, 256>>>(Wq, Wk, Wv, wqkvT);
    trt_kernel<<<(FIN*DD + 255)/256, 256>>>(We, weT, FIN, DD, FIN*DD);
    trt_kernel<<<(LYR*DD*DD + 255)/256, 256>>>(Wout, woutT, DD, DD, LYR*DD*DD);
    trt_kernel<<<(LYR*DD*FF + 255)/256, 256>>>(Wff1, wff1T, DD, FF, LYR*DD*FF);
    trt_kernel<<<(LYR*FF*DD + 255)/256, 256>>>(Wff2, wff2T, FF, DD, LYR*FF*DD);
    maskpack_kernel<<<(BB*NN*(NN/32) + 255)/256, 256>>>(mask, mp);

    // embed: h = relu(x @ We), exact + fp16 copy
    gemm_hc<16><<<dim3(DD/64, ROWS/128), 256, SM16>>>(
        xh, weT, nullptr, nullptr, h, hh, ROWS, FIN, DD, 1);

    for (int l = 0; l < LYR; l++){
        // fused QKV (fp16 out only)
        gemm_hc<32><<<dim3(QKVN/64, ROWS/128), 256, SM32>>>(
            hh, wqkvT + (size_t)l * QKVN * DD, nullptr, nullptr,
            nullptr, qkv, ROWS, DD, QKVN, 0);

        attn_mma<<<BB * HH, 256, ATTN_SMEM>>>(qkv, mp, heads);

        // h = h + heads @ Wout[l]  (exact + fp16)
        gemm_hc<32><<<dim3(DD/64, ROWS/128), 256, SM32>>>(
            heads, woutT + (size_t)l * DD * DD, nullptr, h,
            h, hh, ROWS, DD, DD, 0);

        // ff = relu(h @ Wff1 + bff1)  (fp16 out only)
        gemm_hc<32><<<dim3(FF/64, ROWS/128), 256, SM32>>>(
            hh, wff1T + (size_t)l * FF * DD, bff1 + (size_t)l * FF, nullptr,
            nullptr, ff, ROWS, DD, FF, 1);

        // h = h + ff @ Wff2 + bff2  (exact + fp16)
        gemm_hc<32><<<dim3(DD/64, ROWS/128), 256, SM32>>>(
            ff, wff2T + (size_t)l * DD * FF, bff2 + (size_t)l * DD, h,
            h, hh, ROWS, FF, DD, 0);
    }

    pool_kernel<<<BB, DD>>>(h, Wp, hpp);
    readout_kernel<<<ROWS/128, 128>>>(h, hpp, Wr, br, out);
}